// round 12
// baseline (speedup 1.0000x reference)
#include <cuda_runtime.h>
#include <cstdint>

typedef unsigned long long ull;

#define B_TILE   14           // batches per block (grid 293 ~= 2 balanced blocks per SM)
#define B_PAD    16           // padded batch count for smem regions
#define NTHREADS 256
#define T        64
#define D        128
#define CTILE    16           // columns per weight tile (floats)
#define NTILES   8            // 128 / 16
#define RSTRIDE  20           // padded tile row stride in floats (5 float4, conflict-free)
#define NROWS    576          // wk(128)+wq(128)+wv(128)+wo(128)+V(64)
#define TILE_F   (NROWS * RSTRIDE)   // 11520 floats per buffer

// dynamic smem layout (float offsets)
#define OFF_WS    0
#define OFF_STATE (2 * TILE_F)            // 23040
#define OFF_X     (OFF_STATE + B_PAD*D)   // 25088
#define OFF_V     (OFF_X + B_PAD*T)       // 26112
#define OFF_S     (OFF_V + B_PAD*T)       // 27136
#define OFF_D     (OFF_S + B_PAD)
#define OFF_MN    (OFF_D + B_PAD)
#define OFF_MX    (OFF_MN + B_PAD)
#define SMEM_F    (OFF_MX + B_PAD)        // 27200 floats = 108800 B

__device__ __forceinline__ ull ffma2(ull a, ull b, ull c) {
    ull r;
    asm("fma.rn.f32x2 %0, %1, %2, %3;" : "=l"(r) : "l"(a), "l"(b), "l"(c));
    return r;
}
__device__ __forceinline__ float sum2(ull a) {
    float lo, hi;
    asm("mov.b64 {%0, %1}, %2;" : "=f"(lo), "=f"(hi) : "l"(a));
    return lo + hi;
}
__device__ __forceinline__ float ex2f(float x) {
    float r; asm("ex2.approx.ftz.f32 %0, %1;" : "=f"(r) : "f"(x)); return r;
}
__device__ __forceinline__ void cp16(unsigned int dst, const void* src) {
    asm volatile("cp.async.ca.shared.global [%0], [%1], 16;" :: "r"(dst), "l"(src));
}
__device__ __forceinline__ void cp_commit() {
    asm volatile("cp.async.commit_group;" ::: "memory");
}
template<int N> __device__ __forceinline__ void cp_wait() {
    asm volatile("cp.async.wait_group %0;" :: "n"(N) : "memory");
}

__global__ void __launch_bounds__(NTHREADS, 2)
fused_hyper_attn(const float* __restrict__ x, const float* __restrict__ state,
                 const float* __restrict__ wk_w, const float* __restrict__ wk_b,
                 const float* __restrict__ wq_w, const float* __restrict__ wq_b,
                 const float* __restrict__ wv_w, const float* __restrict__ wv_b,
                 const float* __restrict__ wo_w, const float* __restrict__ wo_b,
                 const float* __restrict__ V_w,  const float* __restrict__ V_b,
                 float* __restrict__ out, int nb)
{
    extern __shared__ __align__(16) float sm[];
    const int t  = threadIdx.x;
    const int b0 = blockIdx.x * B_TILE;
    const int valid = min(B_TILE, nb - b0);       // 14, or 8 on the last block
    const unsigned int sm_u32 = (unsigned int)__cvta_generic_to_shared(sm);

    // ---- stage weight tiles (cp.async, double buffered) ----
    #define STAGE(TI)                                                          \
    do {                                                                       \
        const int c0_ = (TI) * CTILE;                                          \
        const unsigned int wb_ = sm_u32 + (OFF_WS + ((TI) & 1) * TILE_F) * 4;  \
        _Pragma("unroll")                                                      \
        for (int i_ = 0; i_ < 9; i_++) {                                       \
            int q_ = t + i_ * 256;                                             \
            int row_ = q_ >> 2, cq_ = q_ & 3;                                  \
            const float* src_;                                                 \
            if      (i_ < 2) src_ = wk_w + (size_t)row_ * D;                   \
            else if (i_ < 4) src_ = wq_w + (size_t)(row_ - 128) * D;           \
            else if (i_ < 6) src_ = wv_w + (size_t)(row_ - 256) * D;           \
            else if (i_ < 8) src_ = wo_w + (size_t)(row_ - 384) * D;           \
            else             src_ = V_w  + (size_t)(row_ - 512) * D;           \
            cp16(wb_ + (unsigned int)(row_ * RSTRIDE + cq_ * 4) * 4,           \
                 src_ + c0_ + cq_ * 4);                                        \
        }                                                                      \
        cp_commit();                                                           \
    } while (0)

    STAGE(0);
    STAGE(1);

    // ---- stage state (valid x 128, zero-padded to 16) and x likewise ----
    {
        const float4 z4 = make_float4(0.f, 0.f, 0.f, 0.f);
        const float4* gs = (const float4*)(state + (size_t)b0 * D);
        const int vs4 = valid * 32;                   // valid float4s of state
        ((float4*)(sm + OFF_STATE))[t]       = (t       < vs4) ? gs[t]       : z4;
        ((float4*)(sm + OFF_STATE))[t + 256] = (t + 256 < vs4) ? gs[t + 256] : z4;
        const float4* gx = (const float4*)(x + (size_t)b0 * T);
        ((float4*)(sm + OFF_X))[t] = (t < valid * 16) ? gx[t] : z4;
    }
    if (t < B_PAD) { sm[OFF_S + t] = 0.f; sm[OFF_D + t] = 0.f; }
    __syncthreads();   // state/x visible

    // ---- per-batch min/max of x (16 threads, overlapped with tile waits) ----
    if (t < B_PAD) {
        const float* xr = sm + OFF_X + t * T;
        float mn = xr[0], mx = mn;
        #pragma unroll
        for (int k = 1; k < T; k++) {
            float v = xr[k];
            mn = fminf(mn, v); mx = fmaxf(mx, v);
        }
        sm[OFF_MN + t] = mn; sm[OFF_MX + t] = mx;
    }

    // ---- ownership: thread = (batch-half, e). Owns rows e of wk/wq/wv/wo for 8
    //      batches; threads with e<64 (warp-uniform) also own V_w row e. ----
    const int half = t >> 7;               // 0: batches 0-7, 1: batches 8-15
    const int e    = t & 127;
    const int bb0  = half * 8;
    const bool hasV = (e < 64);            // warps 0,1,4,5 — uniform per warp

    ull accK[8], accQ[8], accW[8], accO[8], accVr[8];
    #pragma unroll
    for (int b = 0; b < 8; b++) {
        accK[b] = 0ull; accQ[b] = 0ull; accW[b] = 0ull; accO[b] = 0ull; accVr[b] = 0ull;
    }

    const ulonglong2* st = (const ulonglong2*)(sm + OFF_STATE);  // [16][32] 16B units

    // ---- pipelined main loop over 8 column tiles ----
    for (int ti = 0; ti < NTILES; ti++) {
        if (ti < NTILES - 1) cp_wait<1>(); else cp_wait<0>();
        __syncthreads();                       // tile ti visible to all

        const ulonglong2* wt = (const ulonglong2*)(sm + OFF_WS + (ti & 1) * TILE_F);
        const int jb = ti * 4;                 // float4-column base within state row
        #pragma unroll
        for (int j = 0; j < 4; j++) {
            ulonglong2 wk2 = wt[(e)       * 5 + j];
            ulonglong2 wq2 = wt[(128 + e) * 5 + j];
            ulonglong2 wv2 = wt[(256 + e) * 5 + j];
            ulonglong2 wo2 = wt[(384 + e) * 5 + j];
            #pragma unroll
            for (int b = 0; b < 8; b++) {
                ulonglong2 s = st[(bb0 + b) * 32 + jb + j];
                accK[b] = ffma2(s.x, wk2.x, accK[b]);
                accK[b] = ffma2(s.y, wk2.y, accK[b]);
                accQ[b] = ffma2(s.x, wq2.x, accQ[b]);
                accQ[b] = ffma2(s.y, wq2.y, accQ[b]);
                accW[b] = ffma2(s.x, wv2.x, accW[b]);
                accW[b] = ffma2(s.y, wv2.y, accW[b]);
                accO[b] = ffma2(s.x, wo2.x, accO[b]);
                accO[b] = ffma2(s.y, wo2.y, accO[b]);
            }
            if (hasV) {
                ulonglong2 vv2 = wt[(512 + e) * 5 + j];
                #pragma unroll
                for (int b = 0; b < 8; b++) {
                    ulonglong2 s = st[(bb0 + b) * 32 + jb + j];
                    accVr[b] = ffma2(s.x, vv2.x, accVr[b]);
                    accVr[b] = ffma2(s.y, vv2.y, accVr[b]);
                }
            }
        }

        __syncthreads();                       // all done reading buf[ti&1]
        if (ti + 2 < NTILES) STAGE(ti + 2);
    }

    // ---- finalize: ps = |yk||yq|, pd = |yv||yo| (thread-local), warp-reduce, atomic
    {
        const float bk = wk_b[e], bq = wq_b[e], bv = wv_b[e], bo = wo_b[e];
        float ps[8], pd[8];
        #pragma unroll
        for (int b = 0; b < 8; b++) {
            ps[b] = fabsf(sum2(accK[b]) + bk) * fabsf(sum2(accQ[b]) + bq);
            pd[b] = fabsf(sum2(accW[b]) + bv) * fabsf(sum2(accO[b]) + bo);
        }
        #pragma unroll
        for (int b = 0; b < 8; b++) {
            #pragma unroll
            for (int off = 16; off > 0; off >>= 1) {
                ps[b] += __shfl_xor_sync(0xffffffffu, ps[b], off);
                pd[b] += __shfl_xor_sync(0xffffffffu, pd[b], off);
            }
        }
        if ((t & 31) == 0) {
            #pragma unroll
            for (int b = 0; b < 8; b++) {
                atomicAdd(&sm[OFF_S + bb0 + b], ps[b]);
                atomicAdd(&sm[OFF_D + bb0 + b], pd[b]);
            }
        }
        // v[b][e] for this half's batches (threads with e<64)
        if (hasV) {
            const float vb = V_b[e];
            #pragma unroll
            for (int b = 0; b < 8; b++)
                sm[OFF_V + (bb0 + b) * T + e] = sum2(accVr[b]) + vb;
        }
    }

    __syncthreads();

    // ---- epilogue: per (b,q) softmax over k of c*x_q*x_k (log2 domain), then elu
    {
        const float inv = 0.08838834764831843f * 1.4426950408889634f;  // log2e/sqrt(128)
        #pragma unroll
        for (int i = 0; i < 4; i++) {
            const int idx = t + i * 256;           // 0 .. 1023 ; tasks < 896
            if (idx >= B_TILE * T) break;
            const int b = idx >> 6, q = idx & 63;
            const float* xr = sm + OFF_X + b * T;
            const float4* xr4 = (const float4*)xr;
            float a2 = xr[q] * (sm[OFF_S + b] * inv);
            float m2 = fmaxf(a2 * sm[OFF_MX + b], a2 * sm[OFF_MN + b]);
            float sum = 0.f, ws = 0.f;
            #pragma unroll 4
            for (int j = 0; j < 16; j++) {
                float4 xv = xr4[j];
                float e0 = ex2f(fmaf(a2, xv.x, -m2)); sum += e0; ws = fmaf(e0, xv.x, ws);
                float e1 = ex2f(fmaf(a2, xv.y, -m2)); sum += e1; ws = fmaf(e1, xv.y, ws);
                float e2 = ex2f(fmaf(a2, xv.z, -m2)); sum += e2; ws = fmaf(e2, xv.z, ws);
                float e3 = ex2f(fmaf(a2, xv.w, -m2)); sum += e3; ws = fmaf(e3, xv.w, ws);
            }
            float m = __fdividef(ws, sum);
            float r = fmaf(m, sm[OFF_D + b], sm[OFF_V + b * T + q]);
            if (b < valid)
                out[(size_t)(b0 + b) * T + q] = r > 0.f ? r : expm1f(r);
        }
    }
}

extern "C" void kernel_launch(void* const* d_in, const int* in_sizes, int n_in,
                              void* d_out, int out_size) {
    const float* x     = (const float*)d_in[0];
    const float* state = (const float*)d_in[1];
    const float* wk_w  = (const float*)d_in[2];
    const float* wk_b  = (const float*)d_in[3];
    const float* wq_w  = (const float*)d_in[4];
    const float* wq_b  = (const float*)d_in[5];
    const float* wv_w  = (const float*)d_in[6];
    const float* wv_b  = (const float*)d_in[7];
    const float* wo_w  = (const float*)d_in[8];
    const float* wo_b  = (const float*)d_in[9];
    const float* V_w   = (const float*)d_in[10];
    const float* V_b   = (const float*)d_in[11];

    static int configured = 0;
    if (!configured) {
        cudaFuncSetAttribute(fused_hyper_attn,
                             cudaFuncAttributeMaxDynamicSharedMemorySize,
                             SMEM_F * 4);
        configured = 1;
    }

    int nb   = in_sizes[0] / T;                 // 4096 batches
    int grid = (nb + B_TILE - 1) / B_TILE;      // 293 blocks
    fused_hyper_attn<<<grid, NTHREADS, SMEM_F * 4>>>(x, state,
                                                     wk_w, wk_b, wq_w, wq_b,
                                                     wv_w, wv_b, wo_w, wo_b,
                                                     V_w, V_b, (float*)d_out, nb);
}

// round 13
// speedup vs baseline: 1.2756x; 1.2756x over previous
#include <cuda_runtime.h>
#include <cstdint>

typedef unsigned long long ull;

#define B_TILE   14           // batches per block (grid 293 ~= 2 balanced blocks per SM)
#define B_HALF   7            // batches per thread (half-block)
#define B_PAD    16           // padded batch count for smem regions
#define NTHREADS 256
#define T        64
#define D        128
#define CTILE    16           // columns per weight tile (floats)
#define NTILES   8            // 128 / 16
#define RSTRIDE  20           // padded tile row stride in floats (5 float4, conflict-free)
#define NROWS    576          // wk(128)+wq(128)+wv(128)+wo(128)+V(64)
#define TILE_F   (NROWS * RSTRIDE)   // 11520 floats per buffer

// dynamic smem layout (float offsets)
#define OFF_WS    0
#define OFF_STATE (2 * TILE_F)            // 23040
#define OFF_X     (OFF_STATE + B_PAD*D)   // 25088
#define OFF_V     (OFF_X + B_PAD*T)       // 26112
#define OFF_S     (OFF_V + B_PAD*T)       // 27136
#define OFF_D     (OFF_S + B_PAD)
#define OFF_MN    (OFF_D + B_PAD)
#define OFF_MX    (OFF_MN + B_PAD)
#define SMEM_F    (OFF_MX + B_PAD)        // 27200 floats = 108800 B

__device__ __forceinline__ ull ffma2(ull a, ull b, ull c) {
    ull r;
    asm("fma.rn.f32x2 %0, %1, %2, %3;" : "=l"(r) : "l"(a), "l"(b), "l"(c));
    return r;
}
__device__ __forceinline__ float sum2(ull a) {
    float lo, hi;
    asm("mov.b64 {%0, %1}, %2;" : "=f"(lo), "=f"(hi) : "l"(a));
    return lo + hi;
}
__device__ __forceinline__ float ex2f(float x) {
    float r; asm("ex2.approx.ftz.f32 %0, %1;" : "=f"(r) : "f"(x)); return r;
}
__device__ __forceinline__ void cp16(unsigned int dst, const void* src) {
    asm volatile("cp.async.ca.shared.global [%0], [%1], 16;" :: "r"(dst), "l"(src));
}
__device__ __forceinline__ void cp_commit() {
    asm volatile("cp.async.commit_group;" ::: "memory");
}
template<int N> __device__ __forceinline__ void cp_wait() {
    asm volatile("cp.async.wait_group %0;" :: "n"(N) : "memory");
}

__global__ void __launch_bounds__(NTHREADS, 2)
fused_hyper_attn(const float* __restrict__ x, const float* __restrict__ state,
                 const float* __restrict__ wk_w, const float* __restrict__ wk_b,
                 const float* __restrict__ wq_w, const float* __restrict__ wq_b,
                 const float* __restrict__ wv_w, const float* __restrict__ wv_b,
                 const float* __restrict__ wo_w, const float* __restrict__ wo_b,
                 const float* __restrict__ V_w,  const float* __restrict__ V_b,
                 float* __restrict__ out, int nb)
{
    extern __shared__ __align__(16) float sm[];
    const int t  = threadIdx.x;
    const int b0 = blockIdx.x * B_TILE;
    const int valid = min(B_TILE, nb - b0);       // 14, or 8 on the last block
    const unsigned int sm_u32 = (unsigned int)__cvta_generic_to_shared(sm);

    // ---- stage weight tiles (cp.async, double buffered) ----
    #define STAGE(TI)                                                          \
    do {                                                                       \
        const int c0_ = (TI) * CTILE;                                          \
        const unsigned int wb_ = sm_u32 + (OFF_WS + ((TI) & 1) * TILE_F) * 4;  \
        _Pragma("unroll")                                                      \
        for (int i_ = 0; i_ < 9; i_++) {                                       \
            int q_ = t + i_ * 256;                                             \
            int row_ = q_ >> 2, cq_ = q_ & 3;                                  \
            const float* src_;                                                 \
            if      (i_ < 2) src_ = wk_w + (size_t)row_ * D;                   \
            else if (i_ < 4) src_ = wq_w + (size_t)(row_ - 128) * D;           \
            else if (i_ < 6) src_ = wv_w + (size_t)(row_ - 256) * D;           \
            else if (i_ < 8) src_ = wo_w + (size_t)(row_ - 384) * D;           \
            else             src_ = V_w  + (size_t)(row_ - 512) * D;           \
            cp16(wb_ + (unsigned int)(row_ * RSTRIDE + cq_ * 4) * 4,           \
                 src_ + c0_ + cq_ * 4);                                        \
        }                                                                      \
        cp_commit();                                                           \
    } while (0)

    STAGE(0);
    STAGE(1);

    // ---- stage state (valid x 128, zero-padded) and x likewise ----
    {
        const float4 z4 = make_float4(0.f, 0.f, 0.f, 0.f);
        const float4* gs = (const float4*)(state + (size_t)b0 * D);
        const int vs4 = valid * 32;                   // valid float4s of state
        ((float4*)(sm + OFF_STATE))[t]       = (t       < vs4) ? gs[t]       : z4;
        ((float4*)(sm + OFF_STATE))[t + 256] = (t + 256 < vs4) ? gs[t + 256] : z4;
        const float4* gx = (const float4*)(x + (size_t)b0 * T);
        ((float4*)(sm + OFF_X))[t] = (t < valid * 16) ? gx[t] : z4;
    }
    if (t < B_PAD) { sm[OFF_S + t] = 0.f; sm[OFF_D + t] = 0.f; }
    __syncthreads();   // state/x visible

    // ---- per-batch min/max of x (16 threads, overlapped with tile waits) ----
    if (t < B_PAD) {
        const float* xr = sm + OFF_X + t * T;
        float mn = xr[0], mx = mn;
        #pragma unroll
        for (int k = 1; k < T; k++) {
            float v = xr[k];
            mn = fminf(mn, v); mx = fmaxf(mx, v);
        }
        sm[OFF_MN + t] = mn; sm[OFF_MX + t] = mx;
    }

    // ---- ownership: thread = (batch-half, e). Owns rows e of wk/wq/wv/wo for 7
    //      batches; threads with e<64 (warp-uniform) also own V_w row e. ----
    const int half = t >> 7;               // 0: batches 0-6, 1: batches 7-13
    const int e    = t & 127;
    const int bb0  = half * B_HALF;
    const bool hasV = (e < 64);            // warps 0,1 / 4,5 — uniform per warp

    ull accK[B_HALF], accQ[B_HALF], accW[B_HALF], accO[B_HALF], accVr[B_HALF];
    #pragma unroll
    for (int b = 0; b < B_HALF; b++) {
        accK[b] = 0ull; accQ[b] = 0ull; accW[b] = 0ull; accO[b] = 0ull; accVr[b] = 0ull;
    }

    const ulonglong2* st = (const ulonglong2*)(sm + OFF_STATE);  // [16][32] 16B units

    // ---- pipelined main loop over 8 column tiles ----
    for (int ti = 0; ti < NTILES; ti++) {
        if (ti < NTILES - 1) cp_wait<1>(); else cp_wait<0>();
        __syncthreads();                       // tile ti visible to all

        const ulonglong2* wt = (const ulonglong2*)(sm + OFF_WS + (ti & 1) * TILE_F);
        const int jb = ti * 4;                 // float4-column base within state row
        #pragma unroll
        for (int j = 0; j < 4; j++) {
            ulonglong2 wk2 = wt[(e)       * 5 + j];
            ulonglong2 wq2 = wt[(128 + e) * 5 + j];
            ulonglong2 wv2 = wt[(256 + e) * 5 + j];
            ulonglong2 wo2 = wt[(384 + e) * 5 + j];
            ulonglong2 vv2;
            if (hasV) vv2 = wt[(512 + e) * 5 + j];
            #pragma unroll
            for (int b = 0; b < B_HALF; b++) {
                ulonglong2 s = st[(bb0 + b) * 32 + jb + j];
                accK[b] = ffma2(s.x, wk2.x, accK[b]);
                accK[b] = ffma2(s.y, wk2.y, accK[b]);
                accQ[b] = ffma2(s.x, wq2.x, accQ[b]);
                accQ[b] = ffma2(s.y, wq2.y, accQ[b]);
                accW[b] = ffma2(s.x, wv2.x, accW[b]);
                accW[b] = ffma2(s.y, wv2.y, accW[b]);
                accO[b] = ffma2(s.x, wo2.x, accO[b]);
                accO[b] = ffma2(s.y, wo2.y, accO[b]);
                if (hasV) {
                    accVr[b] = ffma2(s.x, vv2.x, accVr[b]);
                    accVr[b] = ffma2(s.y, vv2.y, accVr[b]);
                }
            }
        }

        __syncthreads();                       // all done reading buf[ti&1]
        if (ti + 2 < NTILES) STAGE(ti + 2);
    }

    // ---- finalize: ps = |yk||yq|, pd = |yv||yo| (thread-local), warp-reduce, atomic
    {
        const float bk = wk_b[e], bq = wq_b[e], bv = wv_b[e], bo = wo_b[e];
        float ps[B_HALF], pd[B_HALF];
        #pragma unroll
        for (int b = 0; b < B_HALF; b++) {
            ps[b] = fabsf(sum2(accK[b]) + bk) * fabsf(sum2(accQ[b]) + bq);
            pd[b] = fabsf(sum2(accW[b]) + bv) * fabsf(sum2(accO[b]) + bo);
        }
        #pragma unroll
        for (int b = 0; b < B_HALF; b++) {
            #pragma unroll
            for (int off = 16; off > 0; off >>= 1) {
                ps[b] += __shfl_xor_sync(0xffffffffu, ps[b], off);
                pd[b] += __shfl_xor_sync(0xffffffffu, pd[b], off);
            }
        }
        if ((t & 31) == 0) {
            #pragma unroll
            for (int b = 0; b < B_HALF; b++) {
                atomicAdd(&sm[OFF_S + bb0 + b], ps[b]);
                atomicAdd(&sm[OFF_D + bb0 + b], pd[b]);
            }
        }
        // v[b][e] for this half's batches (threads with e<64)
        if (hasV) {
            const float vb = V_b[e];
            #pragma unroll
            for (int b = 0; b < B_HALF; b++)
                sm[OFF_V + (bb0 + b) * T + e] = sum2(accVr[b]) + vb;
        }
    }

    __syncthreads();

    // ---- epilogue: per (b,q) softmax over k of c*x_q*x_k (log2 domain), then elu
    {
        const float inv = 0.08838834764831843f * 1.4426950408889634f;  // log2e/sqrt(128)
        #pragma unroll
        for (int i = 0; i < 4; i++) {
            const int idx = t + i * 256;           // 0 .. 1023 ; tasks < 896
            if (idx >= B_TILE * T) break;
            const int b = idx >> 6, q = idx & 63;
            const float* xr = sm + OFF_X + b * T;
            const float4* xr4 = (const float4*)xr;
            float a2 = xr[q] * (sm[OFF_S + b] * inv);
            float m2 = fmaxf(a2 * sm[OFF_MX + b], a2 * sm[OFF_MN + b]);
            float sum = 0.f, ws = 0.f;
            #pragma unroll 4
            for (int j = 0; j < 16; j++) {
                float4 xv = xr4[j];
                float e0 = ex2f(fmaf(a2, xv.x, -m2)); sum += e0; ws = fmaf(e0, xv.x, ws);
                float e1 = ex2f(fmaf(a2, xv.y, -m2)); sum += e1; ws = fmaf(e1, xv.y, ws);
                float e2 = ex2f(fmaf(a2, xv.z, -m2)); sum += e2; ws = fmaf(e2, xv.z, ws);
                float e3 = ex2f(fmaf(a2, xv.w, -m2)); sum += e3; ws = fmaf(e3, xv.w, ws);
            }
            float m = __fdividef(ws, sum);
            float r = fmaf(m, sm[OFF_D + b], sm[OFF_V + b * T + q]);
            if (b < valid)
                out[(size_t)(b0 + b) * T + q] = r > 0.f ? r : expm1f(r);
        }
    }
}

extern "C" void kernel_launch(void* const* d_in, const int* in_sizes, int n_in,
                              void* d_out, int out_size) {
    const float* x     = (const float*)d_in[0];
    const float* state = (const float*)d_in[1];
    const float* wk_w  = (const float*)d_in[2];
    const float* wk_b  = (const float*)d_in[3];
    const float* wq_w  = (const float*)d_in[4];
    const float* wq_b  = (const float*)d_in[5];
    const float* wv_w  = (const float*)d_in[6];
    const float* wv_b  = (const float*)d_in[7];
    const float* wo_w  = (const float*)d_in[8];
    const float* wo_b  = (const float*)d_in[9];
    const float* V_w   = (const float*)d_in[10];
    const float* V_b   = (const float*)d_in[11];

    static int configured = 0;
    if (!configured) {
        cudaFuncSetAttribute(fused_hyper_attn,
                             cudaFuncAttributeMaxDynamicSharedMemorySize,
                             SMEM_F * 4);
        configured = 1;
    }

    int nb   = in_sizes[0] / T;                 // 4096 batches
    int grid = (nb + B_TILE - 1) / B_TILE;      // 293 blocks
    fused_hyper_attn<<<grid, NTHREADS, SMEM_F * 4>>>(x, state,
                                                     wk_w, wk_b, wq_w, wq_b,
                                                     wv_w, wv_b, wo_w, wo_b,
                                                     V_w, V_b, (float*)d_out, nb);
}

// round 14
// speedup vs baseline: 1.2845x; 1.0069x over previous
#include <cuda_runtime.h>
#include <cstdint>

typedef unsigned long long ull;

#define B_TILE   14           // batches per block (grid 293 ~= 2 balanced blocks per SM)
#define B_HALF   7            // batches per thread (half-block)
#define B_PAD    16           // padded batch count for smem regions
#define NTHREADS 256
#define T        64
#define D        128
#define CTILE    16           // columns per weight tile (floats)
#define NTILES   8            // 128 / 16
#define RSTRIDE  20           // padded tile row stride in floats (5 float4, conflict-free)
#define NROWS    576          // wk(128)+wq(128)+wv(128)+wo(128)+V(64)
#define TILE_F   (NROWS * RSTRIDE)   // 11520 floats per buffer

// dynamic smem layout (float offsets)
#define OFF_WS    0
#define OFF_STATE (2 * TILE_F)            // 23040
#define OFF_X     (OFF_STATE + B_PAD*D)   // 25088
#define OFF_V     (OFF_X + B_PAD*T)       // 26112
#define OFF_S     (OFF_V + B_PAD*T)       // 27136
#define OFF_D     (OFF_S + B_PAD)
#define OFF_MN    (OFF_D + B_PAD)
#define OFF_MX    (OFF_MN + B_PAD)
#define SMEM_F    (OFF_MX + B_PAD)        // 27200 floats = 108800 B

__device__ __forceinline__ ull ffma2(ull a, ull b, ull c) {
    ull r;
    asm("fma.rn.f32x2 %0, %1, %2, %3;" : "=l"(r) : "l"(a), "l"(b), "l"(c));
    return r;
}
__device__ __forceinline__ float sum2(ull a) {
    float lo, hi;
    asm("mov.b64 {%0, %1}, %2;" : "=f"(lo), "=f"(hi) : "l"(a));
    return lo + hi;
}
__device__ __forceinline__ float ex2f(float x) {
    float r; asm("ex2.approx.ftz.f32 %0, %1;" : "=f"(r) : "f"(x)); return r;
}
__device__ __forceinline__ void cp16(unsigned int dst, const void* src) {
    asm volatile("cp.async.ca.shared.global [%0], [%1], 16;" :: "r"(dst), "l"(src));
}
__device__ __forceinline__ void cp_commit() {
    asm volatile("cp.async.commit_group;" ::: "memory");
}
template<int N> __device__ __forceinline__ void cp_wait() {
    asm volatile("cp.async.wait_group %0;" :: "n"(N) : "memory");
}

__global__ void __launch_bounds__(NTHREADS, 2)
fused_hyper_attn(const float* __restrict__ x, const float* __restrict__ state,
                 const float* __restrict__ wk_w, const float* __restrict__ wk_b,
                 const float* __restrict__ wq_w, const float* __restrict__ wq_b,
                 const float* __restrict__ wv_w, const float* __restrict__ wv_b,
                 const float* __restrict__ wo_w, const float* __restrict__ wo_b,
                 const float* __restrict__ V_w,  const float* __restrict__ V_b,
                 float* __restrict__ out, int nb)
{
    extern __shared__ __align__(16) float sm[];
    const int t  = threadIdx.x;
    const int b0 = blockIdx.x * B_TILE;
    const int valid = min(B_TILE, nb - b0);       // 14, or 8 on the last block
    const unsigned int sm_u32 = (unsigned int)__cvta_generic_to_shared(sm);

    // ---- stage weight tiles (cp.async, double buffered) ----
    #define STAGE(TI)                                                          \
    do {                                                                       \
        const int c0_ = (TI) * CTILE;                                          \
        const unsigned int wb_ = sm_u32 + (OFF_WS + ((TI) & 1) * TILE_F) * 4;  \
        _Pragma("unroll")                                                      \
        for (int i_ = 0; i_ < 9; i_++) {                                       \
            int q_ = t + i_ * 256;                                             \
            int row_ = q_ >> 2, cq_ = q_ & 3;                                  \
            const float* src_;                                                 \
            if      (i_ < 2) src_ = wk_w + (size_t)row_ * D;                   \
            else if (i_ < 4) src_ = wq_w + (size_t)(row_ - 128) * D;           \
            else if (i_ < 6) src_ = wv_w + (size_t)(row_ - 256) * D;           \
            else if (i_ < 8) src_ = wo_w + (size_t)(row_ - 384) * D;           \
            else             src_ = V_w  + (size_t)(row_ - 512) * D;           \
            cp16(wb_ + (unsigned int)(row_ * RSTRIDE + cq_ * 4) * 4,           \
                 src_ + c0_ + cq_ * 4);                                        \
        }                                                                      \
        cp_commit();                                                           \
    } while (0)

    STAGE(0);
    STAGE(1);

    // ---- stage state (valid x 128, zero-padded) and x likewise ----
    {
        const float4 z4 = make_float4(0.f, 0.f, 0.f, 0.f);
        const float4* gs = (const float4*)(state + (size_t)b0 * D);
        const int vs4 = valid * 32;                   // valid float4s of state
        ((float4*)(sm + OFF_STATE))[t]       = (t       < vs4) ? gs[t]       : z4;
        ((float4*)(sm + OFF_STATE))[t + 256] = (t + 256 < vs4) ? gs[t + 256] : z4;
        const float4* gx = (const float4*)(x + (size_t)b0 * T);
        ((float4*)(sm + OFF_X))[t] = (t < valid * 16) ? gx[t] : z4;
    }
    if (t < B_PAD) { sm[OFF_S + t] = 0.f; sm[OFF_D + t] = 0.f; }
    __syncthreads();   // state/x visible

    // ---- per-batch min/max of x (16 threads, overlapped with tile waits) ----
    if (t < B_PAD) {
        const float* xr = sm + OFF_X + t * T;
        float mn = xr[0], mx = mn;
        #pragma unroll
        for (int k = 1; k < T; k++) {
            float v = xr[k];
            mn = fminf(mn, v); mx = fmaxf(mx, v);
        }
        sm[OFF_MN + t] = mn; sm[OFF_MX + t] = mx;
    }

    // ---- ownership: thread = (batch-half, e). Owns rows e of wk/wq/wv/wo for 7
    //      batches. V row (e & 63): batches 0-3 of the half if e<64, else 4-6.
    //      All predicates warp-uniform; all threads now do ~equal ffma2 work. ----
    const int half = t >> 7;               // 0: batches 0-6, 1: batches 7-13
    const int e    = t & 127;
    const int bb0  = half * B_HALF;
    const int vrow = e & 63;
    const bool vlow = (e < 64);            // warp-uniform
    const int vb0  = vlow ? 0 : 4;         // first V batch (within half)
    const int nvb  = vlow ? 4 : 3;         // number of V batches

    ull accK[B_HALF], accQ[B_HALF], accW[B_HALF], accO[B_HALF], accVr[4];
    #pragma unroll
    for (int b = 0; b < B_HALF; b++) {
        accK[b] = 0ull; accQ[b] = 0ull; accW[b] = 0ull; accO[b] = 0ull;
    }
    #pragma unroll
    for (int i = 0; i < 4; i++) accVr[i] = 0ull;

    const ulonglong2* st = (const ulonglong2*)(sm + OFF_STATE);  // [16][32] 16B units

    // ---- pipelined main loop over 8 column tiles ----
    for (int ti = 0; ti < NTILES; ti++) {
        if (ti < NTILES - 1) cp_wait<1>(); else cp_wait<0>();
        __syncthreads();                       // tile ti visible to all

        const ulonglong2* wt = (const ulonglong2*)(sm + OFF_WS + (ti & 1) * TILE_F);
        const int jb = ti * 4;                 // float4-column base within state row
        #pragma unroll
        for (int j = 0; j < 4; j++) {
            ulonglong2 wk2 = wt[(e)       * 5 + j];
            ulonglong2 wq2 = wt[(128 + e) * 5 + j];
            ulonglong2 wv2 = wt[(256 + e) * 5 + j];
            ulonglong2 wo2 = wt[(384 + e) * 5 + j];
            ulonglong2 vv2 = wt[(512 + vrow) * 5 + j];
            #pragma unroll
            for (int b = 0; b < B_HALF; b++) {
                ulonglong2 s = st[(bb0 + b) * 32 + jb + j];
                accK[b] = ffma2(s.x, wk2.x, accK[b]);
                accK[b] = ffma2(s.y, wk2.y, accK[b]);
                accQ[b] = ffma2(s.x, wq2.x, accQ[b]);
                accQ[b] = ffma2(s.y, wq2.y, accQ[b]);
                accW[b] = ffma2(s.x, wv2.x, accW[b]);
                accW[b] = ffma2(s.y, wv2.y, accW[b]);
                accO[b] = ffma2(s.x, wo2.x, accO[b]);
                accO[b] = ffma2(s.y, wo2.y, accO[b]);
                // V: batches 0-3 on e<64 threads, 4-6 on e>=64 (uniform predicate)
                if ((b < 4) == vlow) {
                    accVr[b & 3] = ffma2(s.x, vv2.x, accVr[b & 3]);
                    accVr[b & 3] = ffma2(s.y, vv2.y, accVr[b & 3]);
                }
            }
        }

        __syncthreads();                       // all done reading buf[ti&1]
        if (ti + 2 < NTILES) STAGE(ti + 2);
    }

    // ---- finalize: ps = |yk||yq|, pd = |yv||yo| (thread-local), warp-reduce, atomic
    {
        const float bk = wk_b[e], bq = wq_b[e], bv = wv_b[e], bo = wo_b[e];
        float ps[B_HALF], pd[B_HALF];
        #pragma unroll
        for (int b = 0; b < B_HALF; b++) {
            ps[b] = fabsf(sum2(accK[b]) + bk) * fabsf(sum2(accQ[b]) + bq);
            pd[b] = fabsf(sum2(accW[b]) + bv) * fabsf(sum2(accO[b]) + bo);
        }
        #pragma unroll
        for (int b = 0; b < B_HALF; b++) {
            #pragma unroll
            for (int off = 16; off > 0; off >>= 1) {
                ps[b] += __shfl_xor_sync(0xffffffffu, ps[b], off);
                pd[b] += __shfl_xor_sync(0xffffffffu, pd[b], off);
            }
        }
        if ((t & 31) == 0) {
            #pragma unroll
            for (int b = 0; b < B_HALF; b++) {
                atomicAdd(&sm[OFF_S + bb0 + b], ps[b]);
                atomicAdd(&sm[OFF_D + bb0 + b], pd[b]);
            }
        }
        // v[b][vrow] for this thread's assigned V batches
        const float vb = V_b[vrow];
        #pragma unroll
        for (int i = 0; i < 4; i++) {
            if (i < nvb)
                sm[OFF_V + (bb0 + vb0 + i) * T + vrow] = sum2(accVr[i]) + vb;
        }
    }

    __syncthreads();

    // ---- epilogue: per (b,q) softmax over k of c*x_q*x_k (log2 domain), then elu
    {
        const float inv = 0.08838834764831843f * 1.4426950408889634f;  // log2e/sqrt(128)
        #pragma unroll
        for (int i = 0; i < 4; i++) {
            const int idx = t + i * 256;           // 0 .. 1023 ; tasks < 896
            if (idx >= B_TILE * T) break;
            const int b = idx >> 6, q = idx & 63;
            const float* xr = sm + OFF_X + b * T;
            const float4* xr4 = (const float4*)xr;
            float a2 = xr[q] * (sm[OFF_S + b] * inv);
            float m2 = fmaxf(a2 * sm[OFF_MX + b], a2 * sm[OFF_MN + b]);
            float sum = 0.f, ws = 0.f;
            #pragma unroll 4
            for (int j = 0; j < 16; j++) {
                float4 xv = xr4[j];
                float e0 = ex2f(fmaf(a2, xv.x, -m2)); sum += e0; ws = fmaf(e0, xv.x, ws);
                float e1 = ex2f(fmaf(a2, xv.y, -m2)); sum += e1; ws = fmaf(e1, xv.y, ws);
                float e2 = ex2f(fmaf(a2, xv.z, -m2)); sum += e2; ws = fmaf(e2, xv.z, ws);
                float e3 = ex2f(fmaf(a2, xv.w, -m2)); sum += e3; ws = fmaf(e3, xv.w, ws);
            }
            float m = __fdividef(ws, sum);
            float r = fmaf(m, sm[OFF_D + b], sm[OFF_V + b * T + q]);
            if (b < valid)
                out[(size_t)(b0 + b) * T + q] = r > 0.f ? r : expm1f(r);
        }
    }
}

extern "C" void kernel_launch(void* const* d_in, const int* in_sizes, int n_in,
                              void* d_out, int out_size) {
    const float* x     = (const float*)d_in[0];
    const float* state = (const float*)d_in[1];
    const float* wk_w  = (const float*)d_in[2];
    const float* wk_b  = (const float*)d_in[3];
    const float* wq_w  = (const float*)d_in[4];
    const float* wq_b  = (const float*)d_in[5];
    const float* wv_w  = (const float*)d_in[6];
    const float* wv_b  = (const float*)d_in[7];
    const float* wo_w  = (const float*)d_in[8];
    const float* wo_b  = (const float*)d_in[9];
    const float* V_w   = (const float*)d_in[10];
    const float* V_b   = (const float*)d_in[11];

    static int configured = 0;
    if (!configured) {
        cudaFuncSetAttribute(fused_hyper_attn,
                             cudaFuncAttributeMaxDynamicSharedMemorySize,
                             SMEM_F * 4);
        configured = 1;
    }

    int nb   = in_sizes[0] / T;                 // 4096 batches
    int grid = (nb + B_TILE - 1) / B_TILE;      // 293 blocks
    fused_hyper_attn<<<grid, NTHREADS, SMEM_F * 4>>>(x, state,
                                                     wk_w, wk_b, wq_w, wq_b,
                                                     wv_w, wv_b, wo_w, wo_b,
                                                     V_w, V_b, (float*)d_out, nb);
}